// round 1
// baseline (speedup 1.0000x reference)
#include <cuda_runtime.h>
#include <math.h>

#define T_  2048
#define C_  1024
#define H_  16
#define D_  64
#define L_  4
#define V_  32000
#define C3_ 3072
#define C4_ 4096

// ---- scratch (no allocation allowed) ----
__device__ float g_x[T_ * C_];
__device__ float g_h[T_ * C_];
__device__ float g_qkv[T_ * C3_];
__device__ float g_y[T_ * C_];
__device__ float g_g[T_ * C4_];

// ---------------- embedding: x = wte[ids] + wpe ----------------
__global__ void embed_k(const int* __restrict__ ids, const float* __restrict__ wte,
                        const float* __restrict__ wpe, float* __restrict__ x) {
    int t = blockIdx.x;
    int id = ids[t];
    const float* wt = wte + (size_t)id * C_;
    const float* wp = wpe + (size_t)t * C_;
    float* xr = x + (size_t)t * C_;
    for (int c = threadIdx.x; c < C_; c += blockDim.x)
        xr[c] = wt[c] + wp[c];
}

// ---------------- layernorm ----------------
__global__ __launch_bounds__(256) void ln_k(const float* __restrict__ x,
                                            const float* __restrict__ w,
                                            const float* __restrict__ b,
                                            float* __restrict__ out) {
    int row = blockIdx.x;
    int tid = threadIdx.x;
    const float* xr = x + (size_t)row * C_;
    float v[4];
    float s = 0.f, ss = 0.f;
#pragma unroll
    for (int i = 0; i < 4; i++) {
        v[i] = xr[tid + i * 256];
        s += v[i];
        ss += v[i] * v[i];
    }
#pragma unroll
    for (int o = 16; o > 0; o >>= 1) {
        s  += __shfl_xor_sync(0xffffffffu, s, o);
        ss += __shfl_xor_sync(0xffffffffu, ss, o);
    }
    __shared__ float rs[8], rss[8];
    __shared__ float stats[2];
    int wid = tid >> 5;
    if ((tid & 31) == 0) { rs[wid] = s; rss[wid] = ss; }
    __syncthreads();
    if (tid == 0) {
        float ts = 0.f, tss = 0.f;
#pragma unroll
        for (int i = 0; i < 8; i++) { ts += rs[i]; tss += rss[i]; }
        float mean = ts * (1.0f / C_);
        float var = tss * (1.0f / C_) - mean * mean;
        stats[0] = mean;
        stats[1] = rsqrtf(var + 1e-5f);
    }
    __syncthreads();
    float mean = stats[0], rstd = stats[1];
    float* outr = out + (size_t)row * C_;
#pragma unroll
    for (int i = 0; i < 4; i++) {
        int c = tid + i * 256;
        outr[c] = (v[i] - mean) * rstd * w[c] + b[c];
    }
}

// ---------------- NT GEMM: C[m,n] = sum_k A[m,k]*B[n,k] (+bias/res/gelu) ----------------
#define BM 128
#define BN 128
#define BK 16

__device__ __forceinline__ float gelu_f(float x) {
    return 0.5f * x * (1.0f + erff(x * 0.70710678118654752f));
}

// MODE bit0: +bias[n]; bit1: += C (residual, read-modify-write); bit2: gelu
template <int MODE>
__global__ __launch_bounds__(256) void gemm_nt(const float* __restrict__ A,
                                               const float* __restrict__ B,
                                               const float* __restrict__ bias,
                                               float* __restrict__ Cmat,
                                               int M, int N, int K) {
    __shared__ float As[BK][BM];
    __shared__ float Bs[BK][BN];
    int tid = threadIdx.x;
    int bm0 = blockIdx.y * BM, bn0 = blockIdx.x * BN;
    int ty = tid >> 4, tx = tid & 15;
    float acc[8][8];
#pragma unroll
    for (int i = 0; i < 8; i++)
#pragma unroll
        for (int j = 0; j < 8; j++) acc[i][j] = 0.f;

    const float* Ab = A + (size_t)bm0 * K;
    const float* Bb = B + (size_t)bn0 * K;

    for (int k0 = 0; k0 < K; k0 += BK) {
#pragma unroll
        for (int i = 0; i < 2; i++) {
            int id = tid + i * 256;
            int r = id >> 2, c4 = (id & 3) * 4;
            float4 va = *(const float4*)(Ab + (size_t)r * K + k0 + c4);
            As[c4 + 0][r] = va.x; As[c4 + 1][r] = va.y;
            As[c4 + 2][r] = va.z; As[c4 + 3][r] = va.w;
            float4 vb = *(const float4*)(Bb + (size_t)r * K + k0 + c4);
            Bs[c4 + 0][r] = vb.x; Bs[c4 + 1][r] = vb.y;
            Bs[c4 + 2][r] = vb.z; Bs[c4 + 3][r] = vb.w;
        }
        __syncthreads();
#pragma unroll
        for (int k = 0; k < BK; k++) {
            float ra[8], rb[8];
            *(float4*)(ra)     = *(const float4*)&As[k][ty * 8];
            *(float4*)(ra + 4) = *(const float4*)&As[k][ty * 8 + 4];
            *(float4*)(rb)     = *(const float4*)&Bs[k][tx * 8];
            *(float4*)(rb + 4) = *(const float4*)&Bs[k][tx * 8 + 4];
#pragma unroll
            for (int i = 0; i < 8; i++)
#pragma unroll
                for (int j = 0; j < 8; j++) acc[i][j] += ra[i] * rb[j];
        }
        __syncthreads();
    }

#pragma unroll
    for (int i = 0; i < 8; i++) {
        int m = bm0 + ty * 8 + i;
#pragma unroll
        for (int j = 0; j < 8; j++) {
            int n = bn0 + tx * 8 + j;
            float v = acc[i][j];
            if (MODE & 1) v += bias[n];
            if (MODE & 4) v = gelu_f(v);
            size_t off = (size_t)m * N + n;
            if (MODE & 2) v += Cmat[off];
            Cmat[off] = v;
        }
    }
}

// ---------------- causal flash attention, fp32, D=64 ----------------
// grid (T/64, H), block 64. Thread = one query row. K/V 64x64 tiles in SMEM.
#define KP 68  // smem pitch (floats), 16B aligned

__global__ __launch_bounds__(64) void attn_k(const float* __restrict__ qkv,
                                             float* __restrict__ y) {
    int qt = blockIdx.x;
    int head = blockIdx.y;
    int tid = threadIdx.x;
    int row = qt * 64 + tid;

    __shared__ float Ks[64 * KP];
    __shared__ float Vs[64 * KP];

    float q[64], o[64];
    const float scale = 0.125f;  // 1/sqrt(64)
    const float* qptr = qkv + (size_t)row * C3_ + head * 64;
#pragma unroll
    for (int d = 0; d < 64; d += 4) {
        float4 t4 = *(const float4*)(qptr + d);
        q[d] = t4.x * scale; q[d + 1] = t4.y * scale;
        q[d + 2] = t4.z * scale; q[d + 3] = t4.w * scale;
    }
#pragma unroll
    for (int d = 0; d < 64; d++) o[d] = 0.f;
    float m = -1e30f, l = 0.f;

    for (int kt = 0; kt <= qt; ++kt) {
        const float* kp = qkv + (size_t)(kt * 64 + tid) * C3_ + C_ + head * 64;
        const float* vp = kp + C_;
#pragma unroll
        for (int d = 0; d < 64; d += 4) {
            *(float4*)&Ks[tid * KP + d] = *(const float4*)(kp + d);
            *(float4*)&Vs[tid * KP + d] = *(const float4*)(vp + d);
        }
        __syncthreads();

        bool diag = (kt == qt);
        int lim = diag ? (tid + 1) : 64;

        for (int jc = 0; jc < 4; ++jc) {
            int jbase = jc * 16;
            if (diag && jbase >= lim) break;

            float s[16];
            float cmax = -1e30f;
#pragma unroll
            for (int jj = 0; jj < 16; jj++) {
                const float4* k4 = (const float4*)&Ks[(jbase + jj) * KP];
                float a = 0.f;
#pragma unroll
                for (int d4 = 0; d4 < 16; d4++) {
                    float4 kv = k4[d4];
                    a += q[d4 * 4] * kv.x + q[d4 * 4 + 1] * kv.y +
                         q[d4 * 4 + 2] * kv.z + q[d4 * 4 + 3] * kv.w;
                }
                if (diag && (jbase + jj) >= lim) a = -1e30f;
                s[jj] = a;
                cmax = fmaxf(cmax, a);
            }
            float nm = fmaxf(m, cmax);
            float f = __expf(m - nm);
            l *= f;
#pragma unroll
            for (int d = 0; d < 64; d++) o[d] *= f;
#pragma unroll
            for (int jj = 0; jj < 16; jj++) {
                float p = __expf(s[jj] - nm);
                l += p;
                const float4* v4 = (const float4*)&Vs[(jbase + jj) * KP];
#pragma unroll
                for (int d4 = 0; d4 < 16; d4++) {
                    float4 vv = v4[d4];
                    o[d4 * 4]     += p * vv.x;
                    o[d4 * 4 + 1] += p * vv.y;
                    o[d4 * 4 + 2] += p * vv.z;
                    o[d4 * 4 + 3] += p * vv.w;
                }
            }
            m = nm;
        }
        __syncthreads();
    }

    float inv = 1.0f / l;
    float* yp = y + (size_t)row * C_ + head * 64;
#pragma unroll
    for (int d = 0; d < 64; d += 4) {
        float4 t4;
        t4.x = o[d] * inv; t4.y = o[d + 1] * inv;
        t4.z = o[d + 2] * inv; t4.w = o[d + 3] * inv;
        *(float4*)(yp + d) = t4;
    }
}

// ---------------- launch ----------------
extern "C" void kernel_launch(void* const* d_in, const int* in_sizes, int n_in,
                              void* d_out, int out_size) {
    const int*   ids   = (const int*)d_in[0];
    const float* wte   = (const float*)d_in[1];
    const float* wpe   = (const float*)d_in[2];
    const float* ln1w  = (const float*)d_in[3];
    const float* ln1b  = (const float*)d_in[4];
    const float* attnw = (const float*)d_in[5];
    const float* attnb = (const float*)d_in[6];
    const float* projw = (const float*)d_in[7];
    const float* projb = (const float*)d_in[8];
    const float* ln2w  = (const float*)d_in[9];
    const float* ln2b  = (const float*)d_in[10];
    const float* fcw   = (const float*)d_in[11];
    const float* fcb   = (const float*)d_in[12];
    const float* fcpw  = (const float*)d_in[13];
    const float* fcpb  = (const float*)d_in[14];
    const float* lnfw  = (const float*)d_in[15];
    const float* lnfb  = (const float*)d_in[16];
    float* out = (float*)d_out;

    float *xp, *hp, *qkvp, *yp, *gp;
    cudaGetSymbolAddress((void**)&xp, g_x);
    cudaGetSymbolAddress((void**)&hp, g_h);
    cudaGetSymbolAddress((void**)&qkvp, g_qkv);
    cudaGetSymbolAddress((void**)&yp, g_y);
    cudaGetSymbolAddress((void**)&gp, g_g);

    embed_k<<<T_, 256>>>(ids, wte, wpe, xp);

    for (int l = 0; l < L_; l++) {
        ln_k<<<T_, 256>>>(xp, ln1w + l * C_, ln1b + l * C_, hp);
        gemm_nt<1><<<dim3(C3_ / BN, T_ / BM), 256>>>(
            hp, attnw + (size_t)l * C3_ * C_, attnb + l * C3_, qkvp, T_, C3_, C_);
        attn_k<<<dim3(T_ / 64, H_), 64>>>(qkvp, yp);
        gemm_nt<3><<<dim3(C_ / BN, T_ / BM), 256>>>(
            yp, projw + (size_t)l * C_ * C_, projb + l * C_, xp, T_, C_, C_);
        ln_k<<<T_, 256>>>(xp, ln2w + l * C_, ln2b + l * C_, hp);
        gemm_nt<5><<<dim3(C4_ / BN, T_ / BM), 256>>>(
            hp, fcw + (size_t)l * C4_ * C_, fcb + l * C4_, gp, T_, C4_, C_);
        gemm_nt<3><<<dim3(C_ / BN, T_ / BM), 256>>>(
            gp, fcpw + (size_t)l * C_ * C4_, fcpb + l * C_, xp, T_, C_, C4_);
    }

    ln_k<<<T_, 256>>>(xp, lnfw, lnfb, hp);
    gemm_nt<0><<<dim3(V_ / BN, T_ / BM), 256>>>(hp, wte, nullptr, out, T_, V_, C_);
}

// round 2
// speedup vs baseline: 2.3328x; 2.3328x over previous
#include <cuda_runtime.h>
#include <math.h>

#define T_  2048
#define C_  1024
#define H_  16
#define D_  64
#define L_  4
#define V_  32000
#define C3_ 3072
#define C4_ 4096

// ---- scratch (no allocation allowed) ----
__device__ float g_x[T_ * C_];
__device__ float g_h[T_ * C_];
__device__ float g_qkv[T_ * C3_];
__device__ float g_y[T_ * C_];
__device__ float g_g[T_ * C4_];

// ---------------- embedding ----------------
__global__ void embed_k(const int* __restrict__ ids, const float* __restrict__ wte,
                        const float* __restrict__ wpe, float* __restrict__ x) {
    int t = blockIdx.x;
    int id = ids[t];
    const float* wt = wte + (size_t)id * C_;
    const float* wp = wpe + (size_t)t * C_;
    float* xr = x + (size_t)t * C_;
    for (int c = threadIdx.x; c < C_; c += blockDim.x)
        xr[c] = wt[c] + wp[c];
}

// ---------------- layernorm ----------------
__global__ __launch_bounds__(256) void ln_k(const float* __restrict__ x,
                                            const float* __restrict__ w,
                                            const float* __restrict__ b,
                                            float* __restrict__ out) {
    int row = blockIdx.x;
    int tid = threadIdx.x;
    const float* xr = x + (size_t)row * C_;
    float v[4];
    float s = 0.f, ss = 0.f;
#pragma unroll
    for (int i = 0; i < 4; i++) {
        v[i] = xr[tid + i * 256];
        s += v[i];
        ss += v[i] * v[i];
    }
#pragma unroll
    for (int o = 16; o > 0; o >>= 1) {
        s  += __shfl_xor_sync(0xffffffffu, s, o);
        ss += __shfl_xor_sync(0xffffffffu, ss, o);
    }
    __shared__ float rs[8], rss[8];
    __shared__ float stats[2];
    int wid = tid >> 5;
    if ((tid & 31) == 0) { rs[wid] = s; rss[wid] = ss; }
    __syncthreads();
    if (tid == 0) {
        float ts = 0.f, tss = 0.f;
#pragma unroll
        for (int i = 0; i < 8; i++) { ts += rs[i]; tss += rss[i]; }
        float mean = ts * (1.0f / C_);
        float var = tss * (1.0f / C_) - mean * mean;
        stats[0] = mean;
        stats[1] = rsqrtf(var + 1e-5f);
    }
    __syncthreads();
    float mean = stats[0], rstd = stats[1];
    float* outr = out + (size_t)row * C_;
#pragma unroll
    for (int i = 0; i < 4; i++) {
        int c = tid + i * 256;
        outr[c] = (v[i] - mean) * rstd * w[c] + b[c];
    }
}

// ---------------- TF32 tensor-core NT GEMM ----------------
// C[m,n] = sum_k A[m,k]*B[n,k], via mma.sync.m16n8k8.tf32
// Block: 256 thr (8 warps, 2x4), tile 128x128x32. Warp tile 64x32.
#define BM 128
#define BN 128
#define BK 32
#define SP 36  // smem pitch (floats)

__device__ __forceinline__ float gelu_f(float x) {
    return 0.5f * x * (1.0f + erff(x * 0.70710678118654752f));
}

__device__ __forceinline__ unsigned tf32_cvt(float x) {
    unsigned y;
    asm("cvt.rna.tf32.f32 %0, %1;" : "=r"(y) : "f"(x));
    return y;
}

__device__ __forceinline__ void mma_tf32(float* c, const unsigned* a, const unsigned* b) {
    asm volatile(
        "mma.sync.aligned.m16n8k8.row.col.f32.tf32.tf32.f32 "
        "{%0,%1,%2,%3}, {%4,%5,%6,%7}, {%8,%9}, {%0,%1,%2,%3};"
        : "+f"(c[0]), "+f"(c[1]), "+f"(c[2]), "+f"(c[3])
        : "r"(a[0]), "r"(a[1]), "r"(a[2]), "r"(a[3]), "r"(b[0]), "r"(b[1]));
}

// MODE bit0: +bias[n]; bit1: += C (residual); bit2: gelu
template <int MODE>
__global__ __launch_bounds__(256) void gemm_nt(const float* __restrict__ A,
                                               const float* __restrict__ B,
                                               const float* __restrict__ bias,
                                               float* __restrict__ Cmat,
                                               int M, int N, int K) {
    __shared__ unsigned As[BM * SP];
    __shared__ unsigned Bs[BN * SP];

    int tid = threadIdx.x;
    int bm0 = blockIdx.y * BM, bn0 = blockIdx.x * BN;
    int wid = tid >> 5, lane = tid & 31;
    int g = lane >> 2, tg = lane & 3;
    int wm = (wid >> 2) * 64;
    int wn = (wid & 3) * 32;

    int lr = tid >> 3;          // 0..31
    int lc = (tid & 7) * 4;     // 0..28

    const float* Ab = A + (size_t)bm0 * K;
    const float* Bb = B + (size_t)bn0 * K;

    float acc[4][4][4];
#pragma unroll
    for (int i = 0; i < 4; i++)
#pragma unroll
        for (int j = 0; j < 4; j++)
#pragma unroll
            for (int r = 0; r < 4; r++) acc[i][j][r] = 0.f;

    float4 pa[4], pb[4];
#pragma unroll
    for (int i = 0; i < 4; i++) {
        pa[i] = *(const float4*)(Ab + (size_t)(lr + 32 * i) * K + lc);
        pb[i] = *(const float4*)(Bb + (size_t)(lr + 32 * i) * K + lc);
    }

    int niter = K / BK;
    for (int it = 0; it < niter; it++) {
        __syncthreads();
#pragma unroll
        for (int i = 0; i < 4; i++) {
            int r = lr + 32 * i;
            unsigned* ap = &As[r * SP + lc];
            ap[0] = tf32_cvt(pa[i].x); ap[1] = tf32_cvt(pa[i].y);
            ap[2] = tf32_cvt(pa[i].z); ap[3] = tf32_cvt(pa[i].w);
            unsigned* bp = &Bs[r * SP + lc];
            bp[0] = tf32_cvt(pb[i].x); bp[1] = tf32_cvt(pb[i].y);
            bp[2] = tf32_cvt(pb[i].z); bp[3] = tf32_cvt(pb[i].w);
        }
        __syncthreads();

        if (it + 1 < niter) {
            int k0 = (it + 1) * BK;
#pragma unroll
            for (int i = 0; i < 4; i++) {
                pa[i] = *(const float4*)(Ab + (size_t)(lr + 32 * i) * K + k0 + lc);
                pb[i] = *(const float4*)(Bb + (size_t)(lr + 32 * i) * K + k0 + lc);
            }
        }

#pragma unroll
        for (int ks = 0; ks < 4; ks++) {
            int k = ks * 8;
            unsigned af[4][4], bf[4][2];
#pragma unroll
            for (int mt = 0; mt < 4; mt++) {
                int mb = wm + mt * 16;
                af[mt][0] = As[(mb + g) * SP + k + tg];
                af[mt][1] = As[(mb + g + 8) * SP + k + tg];
                af[mt][2] = As[(mb + g) * SP + k + tg + 4];
                af[mt][3] = As[(mb + g + 8) * SP + k + tg + 4];
            }
#pragma unroll
            for (int nt = 0; nt < 4; nt++) {
                int nb = wn + nt * 8;
                bf[nt][0] = Bs[(nb + g) * SP + k + tg];
                bf[nt][1] = Bs[(nb + g) * SP + k + tg + 4];
            }
#pragma unroll
            for (int mt = 0; mt < 4; mt++)
#pragma unroll
                for (int nt = 0; nt < 4; nt++)
                    mma_tf32(acc[mt][nt], af[mt], bf[nt]);
        }
    }

    // epilogue
#pragma unroll
    for (int mt = 0; mt < 4; mt++) {
#pragma unroll
        for (int nt = 0; nt < 4; nt++) {
            int n = bn0 + wn + nt * 8 + 2 * tg;
            float bsum0 = 0.f, bsum1 = 0.f;
            if (MODE & 1) { bsum0 = bias[n]; bsum1 = bias[n + 1]; }
#pragma unroll
            for (int h = 0; h < 2; h++) {
                int m = bm0 + wm + mt * 16 + g + h * 8;
                float v0 = acc[mt][nt][2 * h] + bsum0;
                float v1 = acc[mt][nt][2 * h + 1] + bsum1;
                if (MODE & 4) { v0 = gelu_f(v0); v1 = gelu_f(v1); }
                size_t off = (size_t)m * N + n;
                if (MODE & 2) {
                    float2 old = *(const float2*)(Cmat + off);
                    v0 += old.x; v1 += old.y;
                }
                float2 st; st.x = v0; st.y = v1;
                *(float2*)(Cmat + off) = st;
            }
        }
    }
}

// ---------------- causal flash attention, fp32, D=64, 2 threads/query ----------------
#define KP 72  // row pitch (floats); halves at +0 / +36

__global__ __launch_bounds__(128) void attn_k(const float* __restrict__ qkv,
                                              float* __restrict__ y) {
    int qt = blockIdx.x;
    int head = blockIdx.y;
    int tid = threadIdx.x;
    int ql = tid >> 1;      // local query 0..63
    int half = tid & 1;     // d-half
    int row = qt * 64 + ql;
    int hoff = half * 36;

    __shared__ float Ks[64 * KP];
    __shared__ float Vs[64 * KP];

    float q[32], o[32];
    const float scale = 0.125f;
    const float* qp = qkv + (size_t)row * C3_ + head * 64 + half * 32;
#pragma unroll
    for (int d = 0; d < 32; d += 4) {
        float4 t4 = *(const float4*)(qp + d);
        q[d] = t4.x * scale; q[d + 1] = t4.y * scale;
        q[d + 2] = t4.z * scale; q[d + 3] = t4.w * scale;
    }
#pragma unroll
    for (int d = 0; d < 32; d++) o[d] = 0.f;
    float m = -1e30f, l = 0.f;

    for (int kt = 0; kt <= qt; ++kt) {
        const float* kp = qkv + (size_t)(kt * 64 + ql) * C3_ + C_ + head * 64 + half * 32;
        const float* vp = kp + C_;
#pragma unroll
        for (int d = 0; d < 32; d += 4) {
            *(float4*)&Ks[ql * KP + hoff + d] = *(const float4*)(kp + d);
            *(float4*)&Vs[ql * KP + hoff + d] = *(const float4*)(vp + d);
        }
        __syncthreads();

        bool diag = (kt == qt);

        for (int jc = 0; jc < 4; ++jc) {
            int jbase = jc * 16;
            float s[16];
            float cmax = -1e30f;
#pragma unroll
            for (int jj = 0; jj < 16; jj++) {
                int j = jbase + jj;
                const float4* k4 = (const float4*)&Ks[j * KP + hoff];
                float a = 0.f;
#pragma unroll
                for (int d4 = 0; d4 < 8; d4++) {
                    float4 kv = k4[d4];
                    a += q[d4 * 4] * kv.x + q[d4 * 4 + 1] * kv.y +
                         q[d4 * 4 + 2] * kv.z + q[d4 * 4 + 3] * kv.w;
                }
                a += __shfl_xor_sync(0xffffffffu, a, 1);
                if (diag && j > ql) a = -1e30f;
                s[jj] = a;
                cmax = fmaxf(cmax, a);
            }
            float nm = fmaxf(m, cmax);
            float f = __expf(m - nm);
            l *= f;
#pragma unroll
            for (int d = 0; d < 32; d++) o[d] *= f;
#pragma unroll
            for (int jj = 0; jj < 16; jj++) {
                float p = __expf(s[jj] - nm);
                l += p;
                const float4* v4 = (const float4*)&Vs[(jbase + jj) * KP + hoff];
#pragma unroll
                for (int d4 = 0; d4 < 8; d4++) {
                    float4 vv = v4[d4];
                    o[d4 * 4]     += p * vv.x;
                    o[d4 * 4 + 1] += p * vv.y;
                    o[d4 * 4 + 2] += p * vv.z;
                    o[d4 * 4 + 3] += p * vv.w;
                }
            }
            m = nm;
        }
        __syncthreads();
    }

    float inv = 1.0f / l;
    float* yp = y + (size_t)row * C_ + head * 64 + half * 32;
#pragma unroll
    for (int d = 0; d < 32; d += 4) {
        float4 t4;
        t4.x = o[d] * inv; t4.y = o[d + 1] * inv;
        t4.z = o[d + 2] * inv; t4.w = o[d + 3] * inv;
        *(float4*)(yp + d) = t4;
    }
}

// ---------------- launch ----------------
extern "C" void kernel_launch(void* const* d_in, const int* in_sizes, int n_in,
                              void* d_out, int out_size) {
    const int*   ids   = (const int*)d_in[0];
    const float* wte   = (const float*)d_in[1];
    const float* wpe   = (const float*)d_in[2];
    const float* ln1w  = (const float*)d_in[3];
    const float* ln1b  = (const float*)d_in[4];
    const float* attnw = (const float*)d_in[5];
    const float* attnb = (const float*)d_in[6];
    const float* projw = (const float*)d_in[7];
    const float* projb = (const float*)d_in[8];
    const float* ln2w  = (const float*)d_in[9];
    const float* ln2b  = (const float*)d_in[10];
    const float* fcw   = (const float*)d_in[11];
    const float* fcb   = (const float*)d_in[12];
    const float* fcpw  = (const float*)d_in[13];
    const float* fcpb  = (const float*)d_in[14];
    const float* lnfw  = (const float*)d_in[15];
    const float* lnfb  = (const float*)d_in[16];
    float* out = (float*)d_out;

    float *xp, *hp, *qkvp, *yp, *gp;
    cudaGetSymbolAddress((void**)&xp, g_x);
    cudaGetSymbolAddress((void**)&hp, g_h);
    cudaGetSymbolAddress((void**)&qkvp, g_qkv);
    cudaGetSymbolAddress((void**)&yp, g_y);
    cudaGetSymbolAddress((void**)&gp, g_g);

    embed_k<<<T_, 256>>>(ids, wte, wpe, xp);

    for (int l = 0; l < L_; l++) {
        ln_k<<<T_, 256>>>(xp, ln1w + l * C_, ln1b + l * C_, hp);
        gemm_nt<1><<<dim3(C3_ / BN, T_ / BM), 256>>>(
            hp, attnw + (size_t)l * C3_ * C_, attnb + l * C3_, qkvp, T_, C3_, C_);
        attn_k<<<dim3(T_ / 64, H_), 128>>>(qkvp, yp);
        gemm_nt<3><<<dim3(C_ / BN, T_ / BM), 256>>>(
            yp, projw + (size_t)l * C_ * C_, projb + l * C_, xp, T_, C_, C_);
        ln_k<<<T_, 256>>>(xp, ln2w + l * C_, ln2b + l * C_, hp);
        gemm_nt<5><<<dim3(C4_ / BN, T_ / BM), 256>>>(
            hp, fcw + (size_t)l * C4_ * C_, fcb + l * C4_, gp, T_, C4_, C_);
        gemm_nt<3><<<dim3(C_ / BN, T_ / BM), 256>>>(
            gp, fcpw + (size_t)l * C_ * C4_, fcpb + l * C_, xp, T_, C_, C4_);
    }

    ln_k<<<T_, 256>>>(xp, lnfw, lnfb, hp);
    gemm_nt<0><<<dim3(V_ / BN, T_ / BM), 256>>>(hp, wte, nullptr, out, T_, V_, C_);
}

// round 4
// speedup vs baseline: 3.1226x; 1.3385x over previous
#include <cuda_runtime.h>
#include <math.h>

#define T_  2048
#define C_  1024
#define H_  16
#define D_  64
#define L_  4
#define V_  32000
#define C3_ 3072
#define C4_ 4096

// ---- scratch (no allocation allowed) ----
__device__ float g_x[T_ * C_];
__device__ float g_h[T_ * C_];
__device__ float g_qkv[T_ * C3_];
__device__ float g_y[T_ * C_];
__device__ float g_g[T_ * C4_];

// ---------------- embedding ----------------
__global__ void embed_k(const int* __restrict__ ids, const float* __restrict__ wte,
                        const float* __restrict__ wpe, float* __restrict__ x) {
    int t = blockIdx.x;
    int id = ids[t];
    const float* wt = wte + (size_t)id * C_;
    const float* wp = wpe + (size_t)t * C_;
    float* xr = x + (size_t)t * C_;
    for (int c = threadIdx.x; c < C_; c += blockDim.x)
        xr[c] = wt[c] + wp[c];
}

// ---------------- layernorm ----------------
__global__ __launch_bounds__(256) void ln_k(const float* __restrict__ x,
                                            const float* __restrict__ w,
                                            const float* __restrict__ b,
                                            float* __restrict__ out) {
    int row = blockIdx.x;
    int tid = threadIdx.x;
    const float* xr = x + (size_t)row * C_;
    float v[4];
    float s = 0.f, ss = 0.f;
#pragma unroll
    for (int i = 0; i < 4; i++) {
        v[i] = xr[tid + i * 256];
        s += v[i];
        ss += v[i] * v[i];
    }
#pragma unroll
    for (int o = 16; o > 0; o >>= 1) {
        s  += __shfl_xor_sync(0xffffffffu, s, o);
        ss += __shfl_xor_sync(0xffffffffu, ss, o);
    }
    __shared__ float rs[8], rss[8];
    __shared__ float stats[2];
    int wid = tid >> 5;
    if ((tid & 31) == 0) { rs[wid] = s; rss[wid] = ss; }
    __syncthreads();
    if (tid == 0) {
        float ts = 0.f, tss = 0.f;
#pragma unroll
        for (int i = 0; i < 8; i++) { ts += rs[i]; tss += rss[i]; }
        float mean = ts * (1.0f / C_);
        float var = tss * (1.0f / C_) - mean * mean;
        stats[0] = mean;
        stats[1] = rsqrtf(var + 1e-5f);
    }
    __syncthreads();
    float mean = stats[0], rstd = stats[1];
    float* outr = out + (size_t)row * C_;
#pragma unroll
    for (int i = 0; i < 4; i++) {
        int c = tid + i * 256;
        outr[c] = (v[i] - mean) * rstd * w[c] + b[c];
    }
}

// ---------------- common mma helpers ----------------
__device__ __forceinline__ float gelu_f(float x) {
    return 0.5f * x * (1.0f + erff(x * 0.70710678118654752f));
}

__device__ __forceinline__ unsigned tf32_cvt(float x) {
    unsigned y;
    asm("cvt.rna.tf32.f32 %0, %1;" : "=r"(y) : "f"(x));
    return y;
}

__device__ __forceinline__ void mma_tf32(float* c, const unsigned* a, const unsigned* b) {
    asm volatile(
        "mma.sync.aligned.m16n8k8.row.col.f32.tf32.tf32.f32 "
        "{%0,%1,%2,%3}, {%4,%5,%6,%7}, {%8,%9}, {%0,%1,%2,%3};"
        : "+f"(c[0]), "+f"(c[1]), "+f"(c[2]), "+f"(c[3])
        : "r"(a[0]), "r"(a[1]), "r"(a[2]), "r"(a[3]), "r"(b[0]), "r"(b[1]));
}

// ---------------- TF32 tensor-core NT GEMM ----------------
#define BM 128
#define BN 128
#define BK 32
#define SP 36  // smem pitch (floats)

// MODE bit0: +bias[n]; bit1: += C (residual); bit2: gelu
template <int MODE>
__global__ __launch_bounds__(256) void gemm_nt(const float* __restrict__ A,
                                               const float* __restrict__ B,
                                               const float* __restrict__ bias,
                                               float* __restrict__ Cmat,
                                               int M, int N, int K) {
    __shared__ unsigned As[BM * SP];
    __shared__ unsigned Bs[BN * SP];

    int tid = threadIdx.x;
    int bm0 = blockIdx.y * BM, bn0 = blockIdx.x * BN;
    int wid = tid >> 5, lane = tid & 31;
    int g = lane >> 2, tg = lane & 3;
    int wm = (wid >> 2) * 64;
    int wn = (wid & 3) * 32;

    int lr = tid >> 3;          // 0..31
    int lc = (tid & 7) * 4;     // 0..28

    const float* Ab = A + (size_t)bm0 * K;
    const float* Bb = B + (size_t)bn0 * K;

    float acc[4][4][4];
#pragma unroll
    for (int i = 0; i < 4; i++)
#pragma unroll
        for (int j = 0; j < 4; j++)
#pragma unroll
            for (int r = 0; r < 4; r++) acc[i][j][r] = 0.f;

    float4 pa[4], pb[4];
#pragma unroll
    for (int i = 0; i < 4; i++) {
        pa[i] = *(const float4*)(Ab + (size_t)(lr + 32 * i) * K + lc);
        pb[i] = *(const float4*)(Bb + (size_t)(lr + 32 * i) * K + lc);
    }

    int niter = K / BK;
    for (int it = 0; it < niter; it++) {
        __syncthreads();
#pragma unroll
        for (int i = 0; i < 4; i++) {
            int r = lr + 32 * i;
            unsigned* ap = &As[r * SP + lc];
            ap[0] = tf32_cvt(pa[i].x); ap[1] = tf32_cvt(pa[i].y);
            ap[2] = tf32_cvt(pa[i].z); ap[3] = tf32_cvt(pa[i].w);
            unsigned* bp = &Bs[r * SP + lc];
            bp[0] = tf32_cvt(pb[i].x); bp[1] = tf32_cvt(pb[i].y);
            bp[2] = tf32_cvt(pb[i].z); bp[3] = tf32_cvt(pb[i].w);
        }
        __syncthreads();

        if (it + 1 < niter) {
            int k0 = (it + 1) * BK;
#pragma unroll
            for (int i = 0; i < 4; i++) {
                pa[i] = *(const float4*)(Ab + (size_t)(lr + 32 * i) * K + k0 + lc);
                pb[i] = *(const float4*)(Bb + (size_t)(lr + 32 * i) * K + k0 + lc);
            }
        }

#pragma unroll
        for (int ks = 0; ks < 4; ks++) {
            int k = ks * 8;
            unsigned af[4][4], bf[4][2];
#pragma unroll
            for (int mt = 0; mt < 4; mt++) {
                int mb = wm + mt * 16;
                af[mt][0] = As[(mb + g) * SP + k + tg];
                af[mt][1] = As[(mb + g + 8) * SP + k + tg];
                af[mt][2] = As[(mb + g) * SP + k + tg + 4];
                af[mt][3] = As[(mb + g + 8) * SP + k + tg + 4];
            }
#pragma unroll
            for (int nt = 0; nt < 4; nt++) {
                int nb = wn + nt * 8;
                bf[nt][0] = Bs[(nb + g) * SP + k + tg];
                bf[nt][1] = Bs[(nb + g) * SP + k + tg + 4];
            }
#pragma unroll
            for (int mt = 0; mt < 4; mt++)
#pragma unroll
                for (int nt = 0; nt < 4; nt++)
                    mma_tf32(acc[mt][nt], af[mt], bf[nt]);
        }
    }

    // epilogue
#pragma unroll
    for (int mt = 0; mt < 4; mt++) {
#pragma unroll
        for (int nt = 0; nt < 4; nt++) {
            int n = bn0 + wn + nt * 8 + 2 * tg;
            float bsum0 = 0.f, bsum1 = 0.f;
            if (MODE & 1) { bsum0 = bias[n]; bsum1 = bias[n + 1]; }
#pragma unroll
            for (int h = 0; h < 2; h++) {
                int m = bm0 + wm + mt * 16 + g + h * 8;
                float v0 = acc[mt][nt][2 * h] + bsum0;
                float v1 = acc[mt][nt][2 * h + 1] + bsum1;
                if (MODE & 4) { v0 = gelu_f(v0); v1 = gelu_f(v1); }
                size_t off = (size_t)m * N + n;
                if (MODE & 2) {
                    float2 old = *(const float2*)(Cmat + off);
                    v0 += old.x; v1 += old.y;
                }
                float2 st; st.x = v0; st.y = v1;
                *(float2*)(Cmat + off) = st;
            }
        }
    }
}

// ---------------- tensor-core causal flash attention (TF32) ----------------
// Block: 128 thr (4 warps). Block tile = 64 queries x one head.
// Warp w owns 16 query rows. K/V 64x64 tiles in SMEM (TF32, pitch 72).
// After S phase, P is stored into the Ks region (K is dead).
#define AP 72

__global__ __launch_bounds__(128) void attn_k(const float* __restrict__ qkv,
                                              float* __restrict__ y) {
    int qt = blockIdx.x, head = blockIdx.y;
    int tid = threadIdx.x;
    int w = tid >> 5, lane = tid & 31;
    int g = lane >> 2, tg = lane & 3;

    __shared__ unsigned Ks[64 * AP];   // aliased by P after the S phase
    __shared__ unsigned Vs[64 * AP];

    // Q fragments (A layout), pre-scaled
    unsigned qa[8][4];
    {
        const float scale = 0.125f;  // 1/sqrt(64)
        int r0 = qt * 64 + w * 16 + g;
        const float* q0 = qkv + (size_t)r0 * C3_ + head * 64;
        const float* q1 = q0 + (size_t)8 * C3_;
#pragma unroll
        for (int kc = 0; kc < 8; kc++) {
            qa[kc][0] = tf32_cvt(q0[kc * 8 + tg] * scale);
            qa[kc][1] = tf32_cvt(q1[kc * 8 + tg] * scale);
            qa[kc][2] = tf32_cvt(q0[kc * 8 + tg + 4] * scale);
            qa[kc][3] = tf32_cvt(q1[kc * 8 + tg + 4] * scale);
        }
    }

    float o[8][4];
#pragma unroll
    for (int nf = 0; nf < 8; nf++)
#pragma unroll
        for (int r = 0; r < 4; r++) o[nf][r] = 0.f;
    float m0 = -1e30f, m1 = -1e30f, l0 = 0.f, l1 = 0.f;

    int lrow = tid >> 1;
    int lhalf = (tid & 1) * 32;
    int pr0 = (w * 16 + g) * AP;
    int pr1 = pr0 + 8 * AP;

    for (int kt = 0; kt <= qt; ++kt) {
        __syncthreads();  // protect prev iter's Vs + P(Ks) reads
        {
            const float* kp = qkv + (size_t)(kt * 64 + lrow) * C3_ + C_ + head * 64 + lhalf;
            const float* vp = kp + C_;
#pragma unroll
            for (int i = 0; i < 8; i++) {
                float4 kv = *(const float4*)(kp + i * 4);
                unsigned* kd = &Ks[lrow * AP + lhalf + i * 4];
                kd[0] = tf32_cvt(kv.x); kd[1] = tf32_cvt(kv.y);
                kd[2] = tf32_cvt(kv.z); kd[3] = tf32_cvt(kv.w);
                float4 vv = *(const float4*)(vp + i * 4);
                unsigned* vd = &Vs[lrow * AP + lhalf + i * 4];
                vd[0] = tf32_cvt(vv.x); vd[1] = tf32_cvt(vv.y);
                vd[2] = tf32_cvt(vv.z); vd[3] = tf32_cvt(vv.w);
            }
        }
        __syncthreads();

        // S = Q @ K^T  (warp: 16 x 64)
        float s[8][4];
#pragma unroll
        for (int nf = 0; nf < 8; nf++)
#pragma unroll
            for (int r = 0; r < 4; r++) s[nf][r] = 0.f;
#pragma unroll
        for (int kc = 0; kc < 8; kc++) {
            unsigned bf[8][2];
#pragma unroll
            for (int nf = 0; nf < 8; nf++) {
                bf[nf][0] = Ks[(nf * 8 + g) * AP + kc * 8 + tg];
                bf[nf][1] = Ks[(nf * 8 + g) * AP + kc * 8 + tg + 4];
            }
#pragma unroll
            for (int nf = 0; nf < 8; nf++)
                mma_tf32(s[nf], qa[kc], bf[nf]);
        }

        // causal mask on diagonal tile
        if (kt == qt) {
            int r0 = w * 16 + g, r1 = r0 + 8;
#pragma unroll
            for (int nf = 0; nf < 8; nf++) {
                int c0 = nf * 8 + 2 * tg, c1 = c0 + 1;
                if (c0 > r0) s[nf][0] = -1e30f;
                if (c1 > r0) s[nf][1] = -1e30f;
                if (c0 > r1) s[nf][2] = -1e30f;
                if (c1 > r1) s[nf][3] = -1e30f;
            }
        }

        // online softmax
        float mx0 = -1e30f, mx1 = -1e30f;
#pragma unroll
        for (int nf = 0; nf < 8; nf++) {
            mx0 = fmaxf(mx0, fmaxf(s[nf][0], s[nf][1]));
            mx1 = fmaxf(mx1, fmaxf(s[nf][2], s[nf][3]));
        }
        mx0 = fmaxf(mx0, __shfl_xor_sync(0xffffffffu, mx0, 1));
        mx0 = fmaxf(mx0, __shfl_xor_sync(0xffffffffu, mx0, 2));
        mx1 = fmaxf(mx1, __shfl_xor_sync(0xffffffffu, mx1, 1));
        mx1 = fmaxf(mx1, __shfl_xor_sync(0xffffffffu, mx1, 2));

        float nm0 = fmaxf(m0, mx0), nm1 = fmaxf(m1, mx1);
        float f0 = __expf(m0 - nm0), f1 = __expf(m1 - nm1);
        m0 = nm0; m1 = nm1;

        float sum0 = 0.f, sum1 = 0.f;
#pragma unroll
        for (int nf = 0; nf < 8; nf++) {
            s[nf][0] = __expf(s[nf][0] - m0);
            s[nf][1] = __expf(s[nf][1] - m0);
            s[nf][2] = __expf(s[nf][2] - m1);
            s[nf][3] = __expf(s[nf][3] - m1);
            sum0 += s[nf][0] + s[nf][1];
            sum1 += s[nf][2] + s[nf][3];
        }
        sum0 += __shfl_xor_sync(0xffffffffu, sum0, 1);
        sum0 += __shfl_xor_sync(0xffffffffu, sum0, 2);
        sum1 += __shfl_xor_sync(0xffffffffu, sum1, 1);
        sum1 += __shfl_xor_sync(0xffffffffu, sum1, 2);
        l0 = l0 * f0 + sum0;
        l1 = l1 * f1 + sum1;

#pragma unroll
        for (int nf = 0; nf < 8; nf++) {
            o[nf][0] *= f0; o[nf][1] *= f0;
            o[nf][2] *= f1; o[nf][3] *= f1;
        }

        __syncthreads();  // everyone done reading Ks -> safe to alias with P

        // store P (TF32) into Ks alias, own rows only
#pragma unroll
        for (int nf = 0; nf < 8; nf++) {
            int c = nf * 8 + 2 * tg;
            Ks[pr0 + c]     = tf32_cvt(s[nf][0]);
            Ks[pr0 + c + 1] = tf32_cvt(s[nf][1]);
            Ks[pr1 + c]     = tf32_cvt(s[nf][2]);
            Ks[pr1 + c + 1] = tf32_cvt(s[nf][3]);
        }
        __syncwarp();

        // O += P @ V  (warp: 16 x 64, k = 64 keys)
#pragma unroll
        for (int kc = 0; kc < 8; kc++) {
            unsigned pa[4];
            pa[0] = Ks[pr0 + kc * 8 + tg];
            pa[1] = Ks[pr1 + kc * 8 + tg];
            pa[2] = Ks[pr0 + kc * 8 + tg + 4];
            pa[3] = Ks[pr1 + kc * 8 + tg + 4];
#pragma unroll
            for (int nf = 0; nf < 8; nf++) {
                unsigned bv[2];
                bv[0] = Vs[(kc * 8 + tg) * AP + nf * 8 + g];
                bv[1] = Vs[(kc * 8 + tg + 4) * AP + nf * 8 + g];
                mma_tf32(o[nf], pa, bv);
            }
        }
    }

    // epilogue: normalize + write
    float inv0 = 1.0f / l0, inv1 = 1.0f / l1;
    int r0 = qt * 64 + w * 16 + g;
    float* y0 = y + (size_t)r0 * C_ + head * 64;
    float* y1 = y0 + (size_t)8 * C_;
#pragma unroll
    for (int nf = 0; nf < 8; nf++) {
        int c = nf * 8 + 2 * tg;
        float2 t0; t0.x = o[nf][0] * inv0; t0.y = o[nf][1] * inv0;
        *(float2*)(y0 + c) = t0;
        float2 t1; t1.x = o[nf][2] * inv1; t1.y = o[nf][3] * inv1;
        *(float2*)(y1 + c) = t1;
    }
}

// ---------------- launch ----------------
extern "C" void kernel_launch(void* const* d_in, const int* in_sizes, int n_in,
                              void* d_out, int out_size) {
    const int*   ids   = (const int*)d_in[0];
    const float* wte   = (const float*)d_in[1];
    const float* wpe   = (const float*)d_in[2];
    const float* ln1w  = (const float*)d_in[3];
    const float* ln1b  = (const float*)d_in[4];
    const float* attnw = (const float*)d_in[5];
    const float* attnb = (const float*)d_in[6];
    const float* projw = (const float*)d_in[7];
    const float* projb = (const float*)d_in[8];
    const float* ln2w  = (const float*)d_in[9];
    const float* ln2b  = (const float*)d_in[10];
    const float* fcw   = (const float*)d_in[11];
    const float* fcb   = (const float*)d_in[12];
    const float* fcpw  = (const float*)d_in[13];
    const float* fcpb  = (const float*)d_in[14];
    const float* lnfw  = (const float*)d_in[15];
    const float* lnfb  = (const float*)d_in[16];
    float* out = (float*)d_out;

    float *xp, *hp, *qkvp, *yp, *gp;
    cudaGetSymbolAddress((void**)&xp, g_x);
    cudaGetSymbolAddress((void**)&hp, g_h);
    cudaGetSymbolAddress((void**)&qkvp, g_qkv);
    cudaGetSymbolAddress((void**)&yp, g_y);
    cudaGetSymbolAddress((void**)&gp, g_g);

    embed_k<<<T_, 256>>>(ids, wte, wpe, xp);

    for (int l = 0; l < L_; l++) {
        ln_k<<<T_, 256>>>(xp, ln1w + l * C_, ln1b + l * C_, hp);
        gemm_nt<1><<<dim3(C3_ / BN, T_ / BM), 256>>>(
            hp, attnw + (size_t)l * C3_ * C_, attnb + l * C3_, qkvp, T_, C3_, C_);
        attn_k<<<dim3(T_ / 64, H_), 128>>>(qkvp, yp);
        gemm_nt<3><<<dim3(C_ / BN, T_ / BM), 256>>>(
            yp, projw + (size_t)l * C_ * C_, projb + l * C_, xp, T_, C_, C_);
        ln_k<<<T_, 256>>>(xp, ln2w + l * C_, ln2b + l * C_, hp);
        gemm_nt<5><<<dim3(C4_ / BN, T_ / BM), 256>>>(
            hp, fcw + (size_t)l * C4_ * C_, fcb + l * C4_, gp, T_, C4_, C_);
        gemm_nt<3><<<dim3(C_ / BN, T_ / BM), 256>>>(
            gp, fcpw + (size_t)l * C_ * C4_, fcpb + l * C_, xp, T_, C_, C4_);
    }

    ln_k<<<T_, 256>>>(xp, lnfw, lnfb, hp);
    gemm_nt<0><<<dim3(V_ / BN, T_ / BM), 256>>>(hp, wte, nullptr, out, T_, V_, C_);
}

// round 8
// speedup vs baseline: 3.8732x; 1.2404x over previous
#include <cuda_runtime.h>
#include <cuda_fp16.h>
#include <math.h>

#define T_  2048
#define C_  1024
#define H_  16
#define D_  64
#define L_  4
#define V_  32000
#define C3_ 3072
#define C4_ 4096

// ---- scratch (no allocation allowed) ----
__device__ float g_x[T_ * C_];
__device__ float g_h[T_ * C_];
__device__ float g_qkv[T_ * C3_];
__device__ float g_y[T_ * C_];
__device__ float g_g[T_ * C4_];

// ---------------- embedding ----------------
__global__ void embed_k(const int* __restrict__ ids, const float* __restrict__ wte,
                        const float* __restrict__ wpe, float* __restrict__ x) {
    int t = blockIdx.x;
    int id = ids[t];
    const float* wt = wte + (size_t)id * C_;
    const float* wp = wpe + (size_t)t * C_;
    float* xr = x + (size_t)t * C_;
    for (int c = threadIdx.x; c < C_; c += blockDim.x)
        xr[c] = wt[c] + wp[c];
}

// ---------------- layernorm ----------------
__global__ __launch_bounds__(256) void ln_k(const float* __restrict__ x,
                                            const float* __restrict__ w,
                                            const float* __restrict__ b,
                                            float* __restrict__ out) {
    int row = blockIdx.x;
    int tid = threadIdx.x;
    const float* xr = x + (size_t)row * C_;
    float v[4];
    float s = 0.f, ss = 0.f;
#pragma unroll
    for (int i = 0; i < 4; i++) {
        v[i] = xr[tid + i * 256];
        s += v[i];
        ss += v[i] * v[i];
    }
#pragma unroll
    for (int o = 16; o > 0; o >>= 1) {
        s  += __shfl_xor_sync(0xffffffffu, s, o);
        ss += __shfl_xor_sync(0xffffffffu, ss, o);
    }
    __shared__ float rs[8], rss[8];
    __shared__ float stats[2];
    int wid = tid >> 5;
    if ((tid & 31) == 0) { rs[wid] = s; rss[wid] = ss; }
    __syncthreads();
    if (tid == 0) {
        float ts = 0.f, tss = 0.f;
#pragma unroll
        for (int i = 0; i < 8; i++) { ts += rs[i]; tss += rss[i]; }
        float mean = ts * (1.0f / C_);
        float var = tss * (1.0f / C_) - mean * mean;
        stats[0] = mean;
        stats[1] = rsqrtf(var + 1e-5f);
    }
    __syncthreads();
    float mean = stats[0], rstd = stats[1];
    float* outr = out + (size_t)row * C_;
#pragma unroll
    for (int i = 0; i < 4; i++) {
        int c = tid + i * 256;
        outr[c] = (v[i] - mean) * rstd * w[c] + b[c];
    }
}

// ---------------- common helpers ----------------
__device__ __forceinline__ float gelu_f(float x) {
    return 0.5f * x * (1.0f + erff(x * 0.70710678118654752f));
}

__device__ __forceinline__ unsigned tf32_cvt(float x) {
    unsigned y;
    asm("cvt.rna.tf32.f32 %0, %1;" : "=r"(y) : "f"(x));
    return y;
}

__device__ __forceinline__ void mma_tf32(float* c, const unsigned* a, const unsigned* b) {
    asm volatile(
        "mma.sync.aligned.m16n8k8.row.col.f32.tf32.tf32.f32 "
        "{%0,%1,%2,%3}, {%4,%5,%6,%7}, {%8,%9}, {%0,%1,%2,%3};"
        : "+f"(c[0]), "+f"(c[1]), "+f"(c[2]), "+f"(c[3])
        : "r"(a[0]), "r"(a[1]), "r"(a[2]), "r"(a[3]), "r"(b[0]), "r"(b[1]));
}

__device__ __forceinline__ void mma_f16(float* c, const unsigned* a, const unsigned* b) {
    asm volatile(
        "mma.sync.aligned.m16n8k16.row.col.f32.f16.f16.f32 "
        "{%0,%1,%2,%3}, {%4,%5,%6,%7}, {%8,%9}, {%0,%1,%2,%3};"
        : "+f"(c[0]), "+f"(c[1]), "+f"(c[2]), "+f"(c[3])
        : "r"(a[0]), "r"(a[1]), "r"(a[2]), "r"(a[3]), "r"(b[0]), "r"(b[1]));
}

// ---------------- FP16 tensor-core NT GEMM ----------------
// C[m,n] = sum_k A[m,k]*B[n,k], via mma.sync.m16n8k16.f16 (fp32 accumulate).
// Block: 256 thr (8 warps, 2x4), tile 128x128x32. Warp tile 64x32.
#define BM 128
#define BN 128
#define BK 32
#define HP 40  // smem pitch in halves (80 B/row): conflict-free fragment loads

// MODE bit0: +bias[n]; bit1: += C (residual); bit2: gelu
template <int MODE>
__global__ __launch_bounds__(256) void gemm_nt(const float* __restrict__ A,
                                               const float* __restrict__ B,
                                               const float* __restrict__ bias,
                                               float* __restrict__ Cmat,
                                               int M, int N, int K) {
    __shared__ __half As[BM * HP];
    __shared__ __half Bs[BN * HP];

    int tid = threadIdx.x;
    int bm0 = blockIdx.y * BM, bn0 = blockIdx.x * BN;
    int wid = tid >> 5, lane = tid & 31;
    int g = lane >> 2, tg = lane & 3;
    int wm = (wid >> 2) * 64;
    int wn = (wid & 3) * 32;

    int lr = tid >> 3;          // 0..31
    int lc = (tid & 7) * 4;     // 0..28

    const float* Ab = A + (size_t)bm0 * K;
    const float* Bb = B + (size_t)bn0 * K;

    float acc[4][4][4];
#pragma unroll
    for (int i = 0; i < 4; i++)
#pragma unroll
        for (int j = 0; j < 4; j++)
#pragma unroll
            for (int r = 0; r < 4; r++) acc[i][j][r] = 0.f;

    float4 pa[4], pb[4];
#pragma unroll
    for (int i = 0; i < 4; i++) {
        pa[i] = *(const float4*)(Ab + (size_t)(lr + 32 * i) * K + lc);
        pb[i] = *(const float4*)(Bb + (size_t)(lr + 32 * i) * K + lc);
    }

    int niter = K / BK;
    for (int it = 0; it < niter; it++) {
        __syncthreads();
#pragma unroll
        for (int i = 0; i < 4; i++) {
            int r = lr + 32 * i;
            __half2 a0 = __floats2half2_rn(pa[i].x, pa[i].y);
            __half2 a1 = __floats2half2_rn(pa[i].z, pa[i].w);
            uint2 av; av.x = *(unsigned*)&a0; av.y = *(unsigned*)&a1;
            *(uint2*)&As[r * HP + lc] = av;
            __half2 b0 = __floats2half2_rn(pb[i].x, pb[i].y);
            __half2 b1 = __floats2half2_rn(pb[i].z, pb[i].w);
            uint2 bv; bv.x = *(unsigned*)&b0; bv.y = *(unsigned*)&b1;
            *(uint2*)&Bs[r * HP + lc] = bv;
        }
        __syncthreads();

        if (it + 1 < niter) {
            int k0 = (it + 1) * BK;
#pragma unroll
            for (int i = 0; i < 4; i++) {
                pa[i] = *(const float4*)(Ab + (size_t)(lr + 32 * i) * K + k0 + lc);
                pb[i] = *(const float4*)(Bb + (size_t)(lr + 32 * i) * K + k0 + lc);
            }
        }

#pragma unroll
        for (int ks = 0; ks < 2; ks++) {
            int k = ks * 16;  // halves
            unsigned af[4][4], bf[4][2];
#pragma unroll
            for (int mt = 0; mt < 4; mt++) {
                int mb = wm + mt * 16;
                af[mt][0] = *(const unsigned*)&As[(mb + g) * HP + k + tg * 2];
                af[mt][1] = *(const unsigned*)&As[(mb + g + 8) * HP + k + tg * 2];
                af[mt][2] = *(const unsigned*)&As[(mb + g) * HP + k + tg * 2 + 8];
                af[mt][3] = *(const unsigned*)&As[(mb + g + 8) * HP + k + tg * 2 + 8];
            }
#pragma unroll
            for (int nt = 0; nt < 4; nt++) {
                int nb = wn + nt * 8;
                bf[nt][0] = *(const unsigned*)&Bs[(nb + g) * HP + k + tg * 2];
                bf[nt][1] = *(const unsigned*)&Bs[(nb + g) * HP + k + tg * 2 + 8];
            }
#pragma unroll
            for (int mt = 0; mt < 4; mt++)
#pragma unroll
                for (int nt = 0; nt < 4; nt++)
                    mma_f16(acc[mt][nt], af[mt], bf[nt]);
        }
    }

    // epilogue
#pragma unroll
    for (int mt = 0; mt < 4; mt++) {
#pragma unroll
        for (int nt = 0; nt < 4; nt++) {
            int n = bn0 + wn + nt * 8 + 2 * tg;
            float bsum0 = 0.f, bsum1 = 0.f;
            if (MODE & 1) { bsum0 = bias[n]; bsum1 = bias[n + 1]; }
#pragma unroll
            for (int h = 0; h < 2; h++) {
                int m = bm0 + wm + mt * 16 + g + h * 8;
                float v0 = acc[mt][nt][2 * h] + bsum0;
                float v1 = acc[mt][nt][2 * h + 1] + bsum1;
                if (MODE & 4) { v0 = gelu_f(v0); v1 = gelu_f(v1); }
                size_t off = (size_t)m * N + n;
                if (MODE & 2) {
                    float2 old = *(const float2*)(Cmat + off);
                    v0 += old.x; v1 += old.y;
                }
                float2 st; st.x = v0; st.y = v1;
                *(float2*)(Cmat + off) = st;
            }
        }
    }
}

// ---------------- tensor-core causal flash attention (TF32, mma.sync) ----------------
#define AP 72

__global__ __launch_bounds__(128) void attn_k(const float* __restrict__ qkv,
                                              float* __restrict__ y) {
    int qt = blockIdx.x, head = blockIdx.y;
    int tid = threadIdx.x;
    int w = tid >> 5, lane = tid & 31;
    int g = lane >> 2, tg = lane & 3;

    __shared__ unsigned Ks[64 * AP];   // aliased by P after the S phase
    __shared__ unsigned Vs[64 * AP];

    unsigned qa[8][4];
    {
        const float scale = 0.125f;
        int r0 = qt * 64 + w * 16 + g;
        const float* q0 = qkv + (size_t)r0 * C3_ + head * 64;
        const float* q1 = q0 + (size_t)8 * C3_;
#pragma unroll
        for (int kc = 0; kc < 8; kc++) {
            qa[kc][0] = tf32_cvt(q0[kc * 8 + tg] * scale);
            qa[kc][1] = tf32_cvt(q1[kc * 8 + tg] * scale);
            qa[kc][2] = tf32_cvt(q0[kc * 8 + tg + 4] * scale);
            qa[kc][3] = tf32_cvt(q1[kc * 8 + tg + 4] * scale);
        }
    }

    float o[8][4];
#pragma unroll
    for (int nf = 0; nf < 8; nf++)
#pragma unroll
        for (int r = 0; r < 4; r++) o[nf][r] = 0.f;
    float m0 = -1e30f, m1 = -1e30f, l0 = 0.f, l1 = 0.f;

    int lrow = tid >> 1;
    int lhalf = (tid & 1) * 32;
    int pr0 = (w * 16 + g) * AP;
    int pr1 = pr0 + 8 * AP;

    for (int kt = 0; kt <= qt; ++kt) {
        __syncthreads();
        {
            const float* kp = qkv + (size_t)(kt * 64 + lrow) * C3_ + C_ + head * 64 + lhalf;
            const float* vp = kp + C_;
#pragma unroll
            for (int i = 0; i < 8; i++) {
                float4 kv = *(const float4*)(kp + i * 4);
                unsigned* kd = &Ks[lrow * AP + lhalf + i * 4];
                kd[0] = tf32_cvt(kv.x); kd[1] = tf32_cvt(kv.y);
                kd[2] = tf32_cvt(kv.z); kd[3] = tf32_cvt(kv.w);
                float4 vv = *(const float4*)(vp + i * 4);
                unsigned* vd = &Vs[lrow * AP + lhalf + i * 4];
                vd[0] = tf32_cvt(vv.x); vd[1] = tf32_cvt(vv.y);
                vd[2] = tf32_cvt(vv.z); vd[3] = tf32_cvt(vv.w);
            }
        }
        __syncthreads();

        float s[8][4];
#pragma unroll
        for (int nf = 0; nf < 8; nf++)
#pragma unroll
            for (int r = 0; r < 4; r++) s[nf][r] = 0.f;
#pragma unroll
        for (int kc = 0; kc < 8; kc++) {
            unsigned bf[8][2];
#pragma unroll
            for (int nf = 0; nf < 8; nf++) {
                bf[nf][0] = Ks[(nf * 8 + g) * AP + kc * 8 + tg];
                bf[nf][1] = Ks[(nf * 8 + g) * AP + kc * 8 + tg + 4];
            }
#pragma unroll
            for (int nf = 0; nf < 8; nf++)
                mma_tf32(s[nf], qa[kc], bf[nf]);
        }

        if (kt == qt) {
            int r0 = w * 16 + g, r1 = r0 + 8;
#pragma unroll
            for (int nf = 0; nf < 8; nf++) {
                int c0 = nf * 8 + 2 * tg, c1 = c0 + 1;
                if (c0 > r0) s[nf][0] = -1e30f;
                if (c1 > r0) s[nf][1] = -1e30f;
                if (c0 > r1) s[nf][2] = -1e30f;
                if (c1 > r1) s[nf][3] = -1e30f;
            }
        }

        float mx0 = -1e30f, mx1 = -1e30f;
#pragma unroll
        for (int nf = 0; nf < 8; nf++) {
            mx0 = fmaxf(mx0, fmaxf(s[nf][0], s[nf][1]));
            mx1 = fmaxf(mx1, fmaxf(s[nf][2], s[nf][3]));
        }
        mx0 = fmaxf(mx0, __shfl_xor_sync(0xffffffffu, mx0, 1));
        mx0 = fmaxf(mx0, __shfl_xor_sync(0xffffffffu, mx0, 2));
        mx1 = fmaxf(mx1, __shfl_xor_sync(0xffffffffu, mx1, 1));
        mx1 = fmaxf(mx1, __shfl_xor_sync(0xffffffffu, mx1, 2));

        float nm0 = fmaxf(m0, mx0), nm1 = fmaxf(m1, mx1);
        float f0 = __expf(m0 - nm0), f1 = __expf(m1 - nm1);
        m0 = nm0; m1 = nm1;

        float sum0 = 0.f, sum1 = 0.f;
#pragma unroll
        for (int nf = 0; nf < 8; nf++) {
            s[nf][0] = __expf(s[nf][0] - m0);
            s[nf][1] = __expf(s[nf][1] - m0);
            s[nf][2] = __expf(s[nf][2] - m1);
            s[nf][3] = __expf(s[nf][3] - m1);
            sum0 += s[nf][0] + s[nf][1];
            sum1 += s[nf][2] + s[nf][3];
        }
        sum0 += __shfl_xor_sync(0xffffffffu, sum0, 1);
        sum0 += __shfl_xor_sync(0xffffffffu, sum0, 2);
        sum1 += __shfl_xor_sync(0xffffffffu, sum1, 1);
        sum1 += __shfl_xor_sync(0xffffffffu, sum1, 2);
        l0 = l0 * f0 + sum0;
        l1 = l1 * f1 + sum1;

#pragma unroll
        for (int nf = 0; nf < 8; nf++) {
            o[nf][0] *= f0; o[nf][1] *= f0;
            o[nf][2] *= f1; o[nf][3] *= f1;
        }

        __syncthreads();

#pragma unroll
        for (int nf = 0; nf < 8; nf++) {
            int c = nf * 8 + 2 * tg;
            Ks[pr0 + c]     = tf32_cvt(s[nf][0]);
            Ks[pr0 + c + 1] = tf32_cvt(s[nf][1]);
            Ks[pr1 + c]     = tf32_cvt(s[nf][2]);
            Ks[pr1 + c + 1] = tf32_cvt(s[nf][3]);
        }
        __syncwarp();

#pragma unroll
        for (int kc = 0; kc < 8; kc++) {
            unsigned pa[4];
            pa[0] = Ks[pr0 + kc * 8 + tg];
            pa[1] = Ks[pr1 + kc * 8 + tg];
            pa[2] = Ks[pr0 + kc * 8 + tg + 4];
            pa[3] = Ks[pr1 + kc * 8 + tg + 4];
#pragma unroll
            for (int nf = 0; nf < 8; nf++) {
                unsigned bv[2];
                bv[0] = Vs[(kc * 8 + tg) * AP + nf * 8 + g];
                bv[1] = Vs[(kc * 8 + tg + 4) * AP + nf * 8 + g];
                mma_tf32(o[nf], pa, bv);
            }
        }
    }

    float inv0 = 1.0f / l0, inv1 = 1.0f / l1;
    int r0 = qt * 64 + w * 16 + g;
    float* y0 = y + (size_t)r0 * C_ + head * 64;
    float* y1 = y0 + (size_t)8 * C_;
#pragma unroll
    for (int nf = 0; nf < 8; nf++) {
        int c = nf * 8 + 2 * tg;
        float2 t0; t0.x = o[nf][0] * inv0; t0.y = o[nf][1] * inv0;
        *(float2*)(y0 + c) = t0;
        float2 t1; t1.x = o[nf][2] * inv1; t1.y = o[nf][3] * inv1;
        *(float2*)(y1 + c) = t1;
    }
}

// ---------------- launch ----------------
extern "C" void kernel_launch(void* const* d_in, const int* in_sizes, int n_in,
                              void* d_out, int out_size) {
    const int*   ids   = (const int*)d_in[0];
    const float* wte   = (const float*)d_in[1];
    const float* wpe   = (const float*)d_in[2];
    const float* ln1w  = (const float*)d_in[3];
    const float* ln1b  = (const float*)d_in[4];
    const float* attnw = (const float*)d_in[5];
    const float* attnb = (const float*)d_in[6];
    const float* projw = (const float*)d_in[7];
    const float* projb = (const float*)d_in[8];
    const float* ln2w  = (const float*)d_in[9];
    const float* ln2b  = (const float*)d_in[10];
    const float* fcw   = (const float*)d_in[11];
    const float* fcb   = (const float*)d_in[12];
    const float* fcpw  = (const float*)d_in[13];
    const float* fcpb  = (const float*)d_in[14];
    const float* lnfw  = (const float*)d_in[15];
    const float* lnfb  = (const float*)d_in[16];
    float* out = (float*)d_out;

    float *xp, *hp, *qkvp, *yp, *gp;
    cudaGetSymbolAddress((void**)&xp, g_x);
    cudaGetSymbolAddress((void**)&hp, g_h);
    cudaGetSymbolAddress((void**)&qkvp, g_qkv);
    cudaGetSymbolAddress((void**)&yp, g_y);
    cudaGetSymbolAddress((void**)&gp, g_g);

    embed_k<<<T_, 256>>>(ids, wte, wpe, xp);

    for (int l = 0; l < L_; l++) {
        ln_k<<<T_, 256>>>(xp, ln1w + l * C_, ln1b + l * C_, hp);
        gemm_nt<1><<<dim3(C3_ / BN, T_ / BM), 256>>>(
            hp, attnw + (size_t)l * C3_ * C_, attnb + l * C3_, qkvp, T_, C3_, C_);
        attn_k<<<dim3(T_ / 64, H_), 128>>>(qkvp, yp);
        gemm_nt<3><<<dim3(C_ / BN, T_ / BM), 256>>>(
            yp, projw + (size_t)l * C_ * C_, projb + l * C_, xp, T_, C_, C_);
        ln_k<<<T_, 256>>>(xp, ln2w + l * C_, ln2b + l * C_, hp);
        gemm_nt<5><<<dim3(C4_ / BN, T_ / BM), 256>>>(
            hp, fcw + (size_t)l * C4_ * C_, fcb + l * C4_, gp, T_, C4_, C_);
        gemm_nt<3><<<dim3(C_ / BN, T_ / BM), 256>>>(
            gp, fcpw + (size_t)l * C_ * C4_, fcpb + l * C_, xp, T_, C_, C4_);
    }

    ln_k<<<T_, 256>>>(xp, lnfw, lnfb, hp);
    gemm_nt<0><<<dim3(V_ / BN, T_ / BM), 256>>>(hp, wte, nullptr, out, T_, V_, C_);
}

// round 11
// speedup vs baseline: 5.1574x; 1.3316x over previous
#include <cuda_runtime.h>
#include <cuda_fp16.h>
#include <math.h>

#define T_  2048
#define C_  1024
#define H_  16
#define D_  64
#define L_  4
#define V_  32000
#define C3_ 3072
#define C4_ 4096

// ---- scratch (no allocation allowed) ----
__device__ float  g_x[T_ * C_];          // fp32 residual stream
__device__ __half gh_h[T_ * C_];         // LN output (A operand)
__device__ __half gh_qkv[T_ * C3_];
__device__ __half gh_y[T_ * C_];
__device__ __half gh_g[T_ * C4_];
// fp16 weights (converted per launch)
__device__ __half gh_attnw[L_ * C3_ * C_];
__device__ __half gh_projw[L_ * C_ * C_];
__device__ __half gh_fcw[L_ * C4_ * C_];
__device__ __half gh_fcpw[L_ * C_ * C4_];
__device__ __half gh_wte[V_ * C_];

// ---------------- f32 -> f16 conversion ----------------
__global__ void f2h_k(const float* __restrict__ s, __half* __restrict__ d, int n) {
    int stride = gridDim.x * blockDim.x * 4;
    for (int i = (blockIdx.x * blockDim.x + threadIdx.x) * 4; i < n; i += stride) {
        float4 v = *(const float4*)(s + i);
        __half2 h0 = __floats2half2_rn(v.x, v.y);
        __half2 h1 = __floats2half2_rn(v.z, v.w);
        uint2 u; u.x = *(unsigned*)&h0; u.y = *(unsigned*)&h1;
        *(uint2*)(d + i) = u;
    }
}

// ---------------- embedding ----------------
__global__ void embed_k(const int* __restrict__ ids, const float* __restrict__ wte,
                        const float* __restrict__ wpe, float* __restrict__ x) {
    int t = blockIdx.x;
    int id = ids[t];
    const float* wt = wte + (size_t)id * C_;
    const float* wp = wpe + (size_t)t * C_;
    float* xr = x + (size_t)t * C_;
    for (int c = threadIdx.x; c < C_; c += blockDim.x)
        xr[c] = wt[c] + wp[c];
}

// ---------------- layernorm (fp32 in, fp16 out) ----------------
__global__ __launch_bounds__(256) void ln_k(const float* __restrict__ x,
                                            const float* __restrict__ w,
                                            const float* __restrict__ b,
                                            __half* __restrict__ out) {
    int row = blockIdx.x;
    int tid = threadIdx.x;
    const float* xr = x + (size_t)row * C_;
    float4 v = *(const float4*)(xr + tid * 4);
    float s = v.x + v.y + v.z + v.w;
    float ss = v.x * v.x + v.y * v.y + v.z * v.z + v.w * v.w;
#pragma unroll
    for (int o = 16; o > 0; o >>= 1) {
        s  += __shfl_xor_sync(0xffffffffu, s, o);
        ss += __shfl_xor_sync(0xffffffffu, ss, o);
    }
    __shared__ float rs[8], rss[8];
    __shared__ float stats[2];
    int wid = tid >> 5;
    if ((tid & 31) == 0) { rs[wid] = s; rss[wid] = ss; }
    __syncthreads();
    if (tid == 0) {
        float ts = 0.f, tss = 0.f;
#pragma unroll
        for (int i = 0; i < 8; i++) { ts += rs[i]; tss += rss[i]; }
        float mean = ts * (1.0f / C_);
        float var = tss * (1.0f / C_) - mean * mean;
        stats[0] = mean;
        stats[1] = rsqrtf(var + 1e-5f);
    }
    __syncthreads();
    float mean = stats[0], rstd = stats[1];
    const float4 w4 = *(const float4*)(w + tid * 4);
    const float4 b4 = *(const float4*)(b + tid * 4);
    __half2 h0 = __floats2half2_rn((v.x - mean) * rstd * w4.x + b4.x,
                                   (v.y - mean) * rstd * w4.y + b4.y);
    __half2 h1 = __floats2half2_rn((v.z - mean) * rstd * w4.z + b4.z,
                                   (v.w - mean) * rstd * w4.w + b4.w);
    uint2 u; u.x = *(unsigned*)&h0; u.y = *(unsigned*)&h1;
    *(uint2*)(out + (size_t)row * C_ + tid * 4) = u;
}

// ---------------- common helpers ----------------
__device__ __forceinline__ float gelu_f(float x) {
    return 0.5f * x * (1.0f + erff(x * 0.70710678118654752f));
}

__device__ __forceinline__ void mma_f16(float* c, const unsigned* a, const unsigned* b) {
    asm volatile(
        "mma.sync.aligned.m16n8k16.row.col.f32.f16.f16.f32 "
        "{%0,%1,%2,%3}, {%4,%5,%6,%7}, {%8,%9}, {%0,%1,%2,%3};"
        : "+f"(c[0]), "+f"(c[1]), "+f"(c[2]), "+f"(c[3])
        : "r"(a[0]), "r"(a[1]), "r"(a[2]), "r"(a[3]), "r"(b[0]), "r"(b[1]));
}

__device__ __forceinline__ void ldsm_x2_t(unsigned& r0, unsigned& r1, unsigned addr) {
    asm volatile("ldmatrix.sync.aligned.m8n8.x2.trans.shared.b16 {%0,%1}, [%2];"
                 : "=r"(r0), "=r"(r1) : "r"(addr));
}

// ---------------- FP16 NT GEMM, double-buffered SMEM ----------------
// C[m,n] = sum_k A[m,k]*B[n,k], A/B fp16 in gmem. Tile 128x128x32, 8 warps.
#define BM 128
#define BN 128
#define BK 32
#define HP 40  // smem pitch in halves

// MODE bit0: +bias[n]; bit1: += C (residual, float only); bit2: gelu
template <int MODE, typename OutT>
__global__ __launch_bounds__(256) void gemm_h(const __half* __restrict__ A,
                                              const __half* __restrict__ B,
                                              const float* __restrict__ bias,
                                              OutT* __restrict__ Cmat,
                                              int M, int N, int K) {
    __shared__ __half As[2][BM * HP];
    __shared__ __half Bs[2][BN * HP];

    int tid = threadIdx.x;
    int bm0 = blockIdx.y * BM, bn0 = blockIdx.x * BN;
    int wid = tid >> 5, lane = tid & 31;
    int g = lane >> 2, tg = lane & 3;
    int wm = (wid >> 2) * 64;
    int wn = (wid & 3) * 32;

    int lr = tid >> 1;              // 0..127 (row)
    int seg = (tid & 1) * 16;       // 0 / 16 halves (each thread covers 16 halves)

    const __half* Ap = A + (size_t)(bm0 + lr) * K + seg;
    const __half* Bp = B + (size_t)(bn0 + lr) * K + seg;

    float acc[4][4][4];
#pragma unroll
    for (int i = 0; i < 4; i++)
#pragma unroll
        for (int j = 0; j < 4; j++)
#pragma unroll
            for (int r = 0; r < 4; r++) acc[i][j][r] = 0.f;

    // full-coverage staging: 2 x uint4 (16 halves) per thread per operand
    uint4 la0 = *(const uint4*)Ap;
    uint4 la1 = *(const uint4*)(Ap + 8);
    uint4 lb0 = *(const uint4*)Bp;
    uint4 lb1 = *(const uint4*)(Bp + 8);
    *(uint4*)&As[0][lr * HP + seg]     = la0;
    *(uint4*)&As[0][lr * HP + seg + 8] = la1;
    *(uint4*)&Bs[0][lr * HP + seg]     = lb0;
    *(uint4*)&Bs[0][lr * HP + seg + 8] = lb1;
    __syncthreads();

    int niter = K / BK;
    for (int it = 0; it < niter; it++) {
        int st = it & 1;
        if (it + 1 < niter) {
            const __half* An = Ap + (it + 1) * BK;
            const __half* Bn = Bp + (it + 1) * BK;
            la0 = *(const uint4*)An;
            la1 = *(const uint4*)(An + 8);
            lb0 = *(const uint4*)Bn;
            lb1 = *(const uint4*)(Bn + 8);
        }
        const __half* Ast = As[st];
        const __half* Bst = Bs[st];
#pragma unroll
        for (int ks = 0; ks < 2; ks++) {
            int k = ks * 16;
            unsigned af[4][4], bf[4][2];
#pragma unroll
            for (int mt = 0; mt < 4; mt++) {
                int mb = wm + mt * 16;
                af[mt][0] = *(const unsigned*)&Ast[(mb + g) * HP + k + tg * 2];
                af[mt][1] = *(const unsigned*)&Ast[(mb + g + 8) * HP + k + tg * 2];
                af[mt][2] = *(const unsigned*)&Ast[(mb + g) * HP + k + tg * 2 + 8];
                af[mt][3] = *(const unsigned*)&Ast[(mb + g + 8) * HP + k + tg * 2 + 8];
            }
#pragma unroll
            for (int nt = 0; nt < 4; nt++) {
                int nb = wn + nt * 8;
                bf[nt][0] = *(const unsigned*)&Bst[(nb + g) * HP + k + tg * 2];
                bf[nt][1] = *(const unsigned*)&Bst[(nb + g) * HP + k + tg * 2 + 8];
            }
#pragma unroll
            for (int mt = 0; mt < 4; mt++)
#pragma unroll
                for (int nt = 0; nt < 4; nt++)
                    mma_f16(acc[mt][nt], af[mt], bf[nt]);
        }
        if (it + 1 < niter) {
            *(uint4*)&As[st ^ 1][lr * HP + seg]     = la0;
            *(uint4*)&As[st ^ 1][lr * HP + seg + 8] = la1;
            *(uint4*)&Bs[st ^ 1][lr * HP + seg]     = lb0;
            *(uint4*)&Bs[st ^ 1][lr * HP + seg + 8] = lb1;
        }
        __syncthreads();
    }

    // epilogue
#pragma unroll
    for (int mt = 0; mt < 4; mt++) {
#pragma unroll
        for (int nt = 0; nt < 4; nt++) {
            int n = bn0 + wn + nt * 8 + 2 * tg;
            float bsum0 = 0.f, bsum1 = 0.f;
            if (MODE & 1) { bsum0 = bias[n]; bsum1 = bias[n + 1]; }
#pragma unroll
            for (int h = 0; h < 2; h++) {
                int m = bm0 + wm + mt * 16 + g + h * 8;
                float v0 = acc[mt][nt][2 * h] + bsum0;
                float v1 = acc[mt][nt][2 * h + 1] + bsum1;
                if (MODE & 4) { v0 = gelu_f(v0); v1 = gelu_f(v1); }
                size_t off = (size_t)m * N + n;
                if (MODE & 2) {
                    float2 old = *(const float2*)((const float*)Cmat + off);
                    v0 += old.x; v1 += old.y;
                }
                if (sizeof(OutT) == 2) {
                    __half2 hv = __floats2half2_rn(v0, v1);
                    *(__half2*)((__half*)Cmat + off) = hv;
                } else {
                    float2 st2; st2.x = v0; st2.y = v1;
                    *(float2*)((float*)Cmat + off) = st2;
                }
            }
        }
    }
}

// ---------------- FP16 tensor-core causal flash attention ----------------
// Block 128 thr (4 warps), tile 64 queries x one head. P kept in registers.
#define KP2 72  // halves pitch (144 B/row)

__global__ __launch_bounds__(128) void attn_k(const __half* __restrict__ qkv,
                                              __half* __restrict__ y) {
    int qt = blockIdx.x, head = blockIdx.y;
    int tid = threadIdx.x;
    int w = tid >> 5, lane = tid & 31;
    int g = lane >> 2, tg = lane & 3;

    __shared__ __half Ks[64 * KP2];
    __shared__ __half Vs[64 * KP2];

    // Q fragments (pre-scaled by 1/8, exact in fp16)
    unsigned qa[4][4];
    {
        const __half2 sc = __float2half2_rn(0.125f);
        int r0 = qt * 64 + w * 16 + g;
        const __half* q0 = qkv + (size_t)r0 * C3_ + head * 64;
        const __half* q1 = q0 + (size_t)8 * C3_;
#pragma unroll
        for (int kc = 0; kc < 4; kc++) {
            __half2 a0 = __hmul2(*(const __half2*)(q0 + kc * 16 + tg * 2), sc);
            __half2 a1 = __hmul2(*(const __half2*)(q1 + kc * 16 + tg * 2), sc);
            __half2 a2 = __hmul2(*(const __half2*)(q0 + kc * 16 + tg * 2 + 8), sc);
            __half2 a3 = __hmul2(*(const __half2*)(q1 + kc * 16 + tg * 2 + 8), sc);
            qa[kc][0] = *(unsigned*)&a0; qa[kc][1] = *(unsigned*)&a1;
            qa[kc][2] = *(unsigned*)&a2; qa[kc][3] = *(unsigned*)&a3;
        }
    }

    float o[8][4];
#pragma unroll
    for (int nf = 0; nf < 8; nf++)
#pragma unroll
        for (int r = 0; r < 4; r++) o[nf][r] = 0.f;
    float m0 = -1e30f, m1 = -1e30f, l0 = 0.f, l1 = 0.f;

    int lrow = tid >> 1;
    int sec = (tid & 1) * 32;

    for (int kt = 0; kt <= qt; ++kt) {
        __syncthreads();  // readers of previous tile done
        {
            const __half* kp = qkv + (size_t)(kt * 64 + lrow) * C3_ + C_ + head * 64 + sec;
            const __half* vp = kp + C_;
#pragma unroll
            for (int i = 0; i < 4; i++) {
                *(uint4*)&Ks[lrow * KP2 + sec + i * 8] = *(const uint4*)(kp + i * 8);
                *(uint4*)&Vs[lrow * KP2 + sec + i * 8] = *(const uint4*)(vp + i * 8);
            }
        }
        __syncthreads();

        // S = Q @ K^T  (warp: 16 x 64)
        float s[8][4];
#pragma unroll
        for (int nf = 0; nf < 8; nf++)
#pragma unroll
            for (int r = 0; r < 4; r++) s[nf][r] = 0.f;
#pragma unroll
        for (int kc = 0; kc < 4; kc++) {
#pragma unroll
            for (int nf = 0; nf < 8; nf++) {
                unsigned bf[2];
                bf[0] = *(const unsigned*)&Ks[(nf * 8 + g) * KP2 + kc * 16 + tg * 2];
                bf[1] = *(const unsigned*)&Ks[(nf * 8 + g) * KP2 + kc * 16 + tg * 2 + 8];
                mma_f16(s[nf], qa[kc], bf);
            }
        }

        // causal mask on diagonal tile
        if (kt == qt) {
            int r0 = w * 16 + g, r1 = r0 + 8;
#pragma unroll
            for (int nf = 0; nf < 8; nf++) {
                int c0 = nf * 8 + 2 * tg, c1 = c0 + 1;
                if (c0 > r0) s[nf][0] = -1e30f;
                if (c1 > r0) s[nf][1] = -1e30f;
                if (c0 > r1) s[nf][2] = -1e30f;
                if (c1 > r1) s[nf][3] = -1e30f;
            }
        }

        // online softmax
        float mx0 = -1e30f, mx1 = -1e30f;
#pragma unroll
        for (int nf = 0; nf < 8; nf++) {
            mx0 = fmaxf(mx0, fmaxf(s[nf][0], s[nf][1]));
            mx1 = fmaxf(mx1, fmaxf(s[nf][2], s[nf][3]));
        }
        mx0 = fmaxf(mx0, __shfl_xor_sync(0xffffffffu, mx0, 1));
        mx0 = fmaxf(mx0, __shfl_xor_sync(0xffffffffu, mx0, 2));
        mx1 = fmaxf(mx1, __shfl_xor_sync(0xffffffffu, mx1, 1));
        mx1 = fmaxf(mx1, __shfl_xor_sync(0xffffffffu, mx1, 2));

        float nm0 = fmaxf(m0, mx0), nm1 = fmaxf(m1, mx1);
        float f0 = __expf(m0 - nm0), f1 = __expf(m1 - nm1);
        m0 = nm0; m1 = nm1;

        float sum0 = 0.f, sum1 = 0.f;
#pragma unroll
        for (int nf = 0; nf < 8; nf++) {
            s[nf][0] = __expf(s[nf][0] - m0);
            s[nf][1] = __expf(s[nf][1] - m0);
            s[nf][2] = __expf(s[nf][2] - m1);
            s[nf][3] = __expf(s[nf][3] - m1);
            sum0 += s[nf][0] + s[nf][1];
            sum1 += s[nf][2] + s[nf][3];
        }
        sum0 += __shfl_xor_sync(0xffffffffu, sum0, 1);
        sum0 += __shfl_xor_sync(0xffffffffu, sum0, 2);
        sum1 += __shfl_xor_sync(0xffffffffu, sum1, 1);
        sum1 += __shfl_xor_sync(0xffffffffu, sum1, 2);
        l0 = l0 * f0 + sum0;
        l1 = l1 * f1 + sum1;

#pragma unroll
        for (int nf = 0; nf < 8; nf++) {
            o[nf][0] *= f0; o[nf][1] *= f0;
            o[nf][2] *= f1; o[nf][3] *= f1;
        }

        // O += P @ V : P fragments directly from the s registers
#pragma unroll
        for (int kc = 0; kc < 4; kc++) {
            unsigned pa[4];
            __half2 p0 = __floats2half2_rn(s[2 * kc][0], s[2 * kc][1]);
            __half2 p1 = __floats2half2_rn(s[2 * kc][2], s[2 * kc][3]);
            __half2 p2 = __floats2half2_rn(s[2 * kc + 1][0], s[2 * kc + 1][1]);
            __half2 p3 = __floats2half2_rn(s[2 * kc + 1][2], s[2 * kc + 1][3]);
            pa[0] = *(unsigned*)&p0; pa[1] = *(unsigned*)&p1;
            pa[2] = *(unsigned*)&p2; pa[3] = *(unsigned*)&p3;
#pragma unroll
            for (int nf = 0; nf < 8; nf++) {
                unsigned b0, b1;
                unsigned addr = (unsigned)__cvta_generic_to_shared(
                    &Vs[(kc * 16 + (lane & 15)) * KP2 + nf * 8]);
                ldsm_x2_t(b0, b1, addr);
                unsigned bv[2] = {b0, b1};
                mma_f16(o[nf], pa, bv);
            }
        }
    }

    // epilogue: normalize + write fp16
    float inv0 = 1.0f / l0, inv1 = 1.0f / l1;
    int r0 = qt * 64 + w * 16 + g;
    __half* y0 = y + (size_t)r0 * C_ + head * 64;
    __half* y1 = y0 + (size_t)8 * C_;
#pragma unroll
    for (int nf = 0; nf < 8; nf++) {
        int c = nf * 8 + 2 * tg;
        *(__half2*)(y0 + c) = __floats2half2_rn(o[nf][0] * inv0, o[nf][1] * inv0);
        *(__half2*)(y1 + c) = __floats2half2_rn(o[nf][2] * inv1, o[nf][3] * inv1);
    }
}

// ---------------- launch ----------------
extern "C" void kernel_launch(void* const* d_in, const int* in_sizes, int n_in,
                              void* d_out, int out_size) {
    const int*   ids   = (const int*)d_in[0];
    const float* wte   = (const float*)d_in[1];
    const float* wpe   = (const float*)d_in[2];
    const float* ln1w  = (const float*)d_in[3];
    const float* ln1b  = (const float*)d_in[4];
    const float* attnw = (const float*)d_in[5];
    const float* attnb = (const float*)d_in[6];
    const float* projw = (const float*)d_in[7];
    const float* projb = (const float*)d_in[8];
    const float* ln2w  = (const float*)d_in[9];
    const float* ln2b  = (const float*)d_in[10];
    const float* fcw   = (const float*)d_in[11];
    const float* fcb   = (const float*)d_in[12];
    const float* fcpw  = (const float*)d_in[13];
    const float* fcpb  = (const float*)d_in[14];
    const float* lnfw  = (const float*)d_in[15];
    const float* lnfb  = (const float*)d_in[16];
    float* out = (float*)d_out;

    float* xp;
    __half *hp, *qkvp, *yp, *gp;
    __half *wA, *wP, *wF, *wFP, *wT;
    cudaGetSymbolAddress((void**)&xp, g_x);
    cudaGetSymbolAddress((void**)&hp, gh_h);
    cudaGetSymbolAddress((void**)&qkvp, gh_qkv);
    cudaGetSymbolAddress((void**)&yp, gh_y);
    cudaGetSymbolAddress((void**)&gp, gh_g);
    cudaGetSymbolAddress((void**)&wA, gh_attnw);
    cudaGetSymbolAddress((void**)&wP, gh_projw);
    cudaGetSymbolAddress((void**)&wF, gh_fcw);
    cudaGetSymbolAddress((void**)&wFP, gh_fcpw);
    cudaGetSymbolAddress((void**)&wT, gh_wte);

    // weight conversions (graph-capturable, deterministic)
    f2h_k<<<2048, 256>>>(attnw, wA, L_ * C3_ * C_);
    f2h_k<<<2048, 256>>>(projw, wP, L_ * C_ * C_);
    f2h_k<<<2048, 256>>>(fcw, wF, L_ * C4_ * C_);
    f2h_k<<<2048, 256>>>(fcpw, wFP, L_ * C_ * C4_);
    f2h_k<<<4096, 256>>>(wte, wT, V_ * C_);

    embed_k<<<T_, 256>>>(ids, wte, wpe, xp);

    for (int l = 0; l < L_; l++) {
        ln_k<<<T_, 256>>>(xp, ln1w + l * C_, ln1b + l * C_, hp);
        gemm_h<1, __half><<<dim3(C3_ / BN, T_ / BM), 256>>>(
            hp, wA + (size_t)l * C3_ * C_, attnb + l * C3_, qkvp, T_, C3_, C_);
        attn_k<<<dim3(T_ / 64, H_), 128>>>(qkvp, yp);
        gemm_h<3, float><<<dim3(C_ / BN, T_ / BM), 256>>>(
            yp, wP + (size_t)l * C_ * C_, projb + l * C_, xp, T_, C_, C_);
        ln_k<<<T_, 256>>>(xp, ln2w + l * C_, ln2b + l * C_, hp);
        gemm_h<5, __half><<<dim3(C4_ / BN, T_ / BM), 256>>>(
            hp, wF + (size_t)l * C4_ * C_, fcb + l * C4_, gp, T_, C4_, C_);
        gemm_h<3, float><<<dim3(C_ / BN, T_ / BM), 256>>>(
            gp, wFP + (size_t)l * C_ * C4_, fcpb + l * C_, xp, T_, C_, C4_);
    }

    ln_k<<<T_, 256>>>(xp, lnfw, lnfb, hp);
    gemm_h<0, float><<<dim3(V_ / BN, T_ / BM), 256>>>(
        hp, wT, nullptr, out, T_, V_, C_);
}